// round 11
// baseline (speedup 1.0000x reference)
#include <cuda_runtime.h>
#include <cuda_bf16.h>

#define BATCH 16384
#define FEAT 512
#define NCLS 100000
#define ALPHA 0.5f
#define LAMDA 0.003f

// Block layout of the mega kernel: fused blocks FIRST (their gather latency
// hides behind abundant co-resident copy work), copy blocks last (pure
// bandwidth keeps DRAM saturated through the tail waves).
#define FUSED_BLOCKS (BATCH / 2)                       // 8192 (2 samples/block)
#define COPY_CHUNKS  (NCLS * (FEAT / 4) / 4)           // 3,200,000 64B chunks
#define COPY_BLOCKS  ((COPY_CHUNKS + 255) / 256)       // 12500

// Scratch (allocation-free __device__ globals).
__device__ int g_counts[NCLS];
__device__ int g_dup_list[BATCH];   // sample indices whose class has cnt>1
__device__ int g_dup_n;

__global__ void zero_counts_kernel() {
    int i = blockIdx.x * blockDim.x + threadIdx.x;
    if (i < NCLS) g_counts[i] = 0;
    if (i == 0) g_dup_n = 0;
}

__global__ void count_kernel(const int* __restrict__ targets) {
    int i = blockIdx.x * blockDim.x + threadIdx.x;
    if (i < BATCH) atomicAdd(&g_counts[targets[i]], 1);
}

// Compact the ~1.6% of samples belonging to duplicate classes into a list,
// so dup_kernel doesn't pay 16384 blocks of early-exit overhead.
__global__ void compact_dups_kernel(const int* __restrict__ targets) {
    int i = blockIdx.x * blockDim.x + threadIdx.x;
    if (i < BATCH && g_counts[targets[i]] > 1) {
        int slot = atomicAdd(&g_dup_n, 1);
        g_dup_list[slot] = i;
    }
}

// One grid doing both jobs so the DRAM pipe never drains:
//  - blocks [0, FUSED_BLOCKS): loss/tw + direct center rewrite (cnt==1)
//  - blocks [FUSED_BLOCKS, +COPY_BLOCKS): streaming copy of center rows,
//    skipping cnt==1 rows (owned by the fused half). cnt>1 rows ARE copied
//    (they are the accumulation base for dup_kernel, which runs after).
__global__ __launch_bounds__(256) void mega_kernel(
    const float4* __restrict__ inputs,
    const float4* __restrict__ centers,
    const float*  __restrict__ wpc,
    const int*    __restrict__ targets,
    float4* __restrict__ loss_out,
    float4* __restrict__ tw_out,
    float4* __restrict__ new_centers) {

    const int bid = blockIdx.x;

    if (bid < FUSED_BLOCKS) {
        // ---- fused half: 2 samples per block, 128 threads each ----
        const int group = threadIdx.x >> 7;         // 0..1
        const int d4    = threadIdx.x & 127;        // 0..127
        const int b = bid * 2 + group;

        const int t   = __ldg(&targets[b]);
        const int cnt = g_counts[t];
        const float w = LAMDA * __ldg(&wpc[t]);
        const float s = ALPHA / (1.0f + (float)cnt);

        const size_t ib = (size_t)b * (FEAT / 4) + d4;
        const size_t ic = (size_t)t * (FEAT / 4) + d4;
        const float4 x = inputs[ib];
        const float4 c = centers[ic];

        float4 l;
        float dx;
        dx = x.x - c.x; l.x = 0.5f * dx * dx;
        dx = x.y - c.y; l.y = 0.5f * dx * dx;
        dx = x.z - c.z; l.z = 0.5f * dx * dx;
        dx = x.w - c.w; l.w = 0.5f * dx * dx;

        loss_out[ib] = l;
        tw_out[ib]   = make_float4(w, w, w, w);

        if (cnt == 1) {
            // Sole sample of its class: full row rewrite, no atomics.
            new_centers[ic] = make_float4(c.x - s * x.x, c.y - s * x.y,
                                          c.z - s * x.z, c.w - s * x.w);
        }
        // cnt > 1: handled by dup_kernel after the base row is copied.
    } else {
        // ---- copy half: 64B (4 float4) per thread, one row per thread ----
        const int tchunk = (bid - FUSED_BLOCKS) * 256 + threadIdx.x;
        const size_t i = (size_t)tchunk * 4;        // float4 index
        const int row = (int)(i >> 7);              // 128 float4 per row
        if (row >= NCLS) return;
        if (g_counts[row] == 1) return;             // fused half owns it
        float4 v0 = __ldcs(&centers[i + 0]);
        float4 v1 = __ldcs(&centers[i + 1]);
        float4 v2 = __ldcs(&centers[i + 2]);
        float4 v3 = __ldcs(&centers[i + 3]);
        __stcs(&new_centers[i + 0], v0);
        __stcs(&new_centers[i + 1], v1);
        __stcs(&new_centers[i + 2], v2);
        __stcs(&new_centers[i + 3], v3);
    }
}

// Persistent post-pass over the compacted duplicate list (~1.4k entries):
// accumulate -s*x onto the copied base row. Fixed small grid.
#define DUP_GRID 296
__global__ __launch_bounds__(128) void dup_kernel(
    const float4* __restrict__ inputs,
    const int*    __restrict__ targets,
    float* __restrict__ new_centers) {

    const int n = g_dup_n;
    const int d4 = threadIdx.x;
    for (int e = blockIdx.x; e < n; e += DUP_GRID) {
        const int b = g_dup_list[e];
        const int t = __ldg(&targets[b]);
        const float s = ALPHA / (1.0f + (float)g_counts[t]);
        const float4 x = inputs[(size_t)b * (FEAT / 4) + d4];
        float* dst = new_centers + (size_t)t * FEAT + d4 * 4;
        atomicAdd(dst + 0, -s * x.x);
        atomicAdd(dst + 1, -s * x.y);
        atomicAdd(dst + 2, -s * x.z);
        atomicAdd(dst + 3, -s * x.w);
    }
}

extern "C" void kernel_launch(void* const* d_in, const int* in_sizes, int n_in,
                              void* d_out, int out_size) {
    const float* inputs  = (const float*)d_in[0];   // [BATCH, FEAT]
    const float* centers = (const float*)d_in[1];   // [NCLS, FEAT]
    const float* wpc     = (const float*)d_in[2];   // [NCLS]
    const int*   targets = (const int*)d_in[3];     // [BATCH]

    float* out  = (float*)d_out;
    float* loss = out;                                  // [BATCH, FEAT]
    float* tw   = out + (size_t)BATCH * FEAT;           // [BATCH, FEAT]
    float* newc = out + (size_t)2 * BATCH * FEAT;       // [NCLS, FEAT]

    zero_counts_kernel<<<(NCLS + 255) / 256, 256>>>();
    count_kernel<<<(BATCH + 255) / 256, 256>>>(targets);
    compact_dups_kernel<<<(BATCH + 255) / 256, 256>>>(targets);

    mega_kernel<<<FUSED_BLOCKS + COPY_BLOCKS, 256>>>(
        (const float4*)inputs, (const float4*)centers, wpc, targets,
        (float4*)loss, (float4*)tw, (float4*)newc);

    dup_kernel<<<DUP_GRID, 128>>>((const float4*)inputs, targets, newc);
}